// round 1
// baseline (speedup 1.0000x reference)
#include <cuda_runtime.h>
#include <math.h>

#define D 64
#define MAXN 20480
#define NSPLIT 4

// Scratch (no allocation allowed in kernel_launch)
__device__ float g_fbn[MAXN * D];
__device__ float g_twn[MAXN * D];
__device__ float g_bestV[NSPLIT * MAXN];
__device__ int   g_bestI[NSPLIT * MAXN];

// ---------------------------------------------------------------------------
// Phase 1: row L2-normalize (warp per row)
// ---------------------------------------------------------------------------
__global__ void __launch_bounds__(256) normalize_kernel(const float* __restrict__ in,
                                                        float* __restrict__ outp, int n) {
    int w = threadIdx.x >> 5, lane = threadIdx.x & 31;
    int row = blockIdx.x * 8 + w;
    if (row >= n) return;
    float2 v = reinterpret_cast<const float2*>(in + (size_t)row * D)[lane];
    float ss = v.x * v.x + v.y * v.y;
    #pragma unroll
    for (int off = 16; off; off >>= 1) ss += __shfl_xor_sync(0xffffffffu, ss, off);
    float nrm = sqrtf(ss);
    float scale = 1.0f / fmaxf(nrm, 1e-8f);
    float2 o; o.x = v.x * scale; o.y = v.y * scale;
    reinterpret_cast<float2*>(outp + (size_t)row * D)[lane] = o;
}

// ---------------------------------------------------------------------------
// Phase 2: fused fp32 GEMM + row argmax.
// Block = 256 threads, BM=64 fb rows, BN=64 tw cols per chunk, K=64 fully
// resident. Tiles stored K-major [k][m] with stride 68 (pad) -> conflict-free
// LDS.128 reads of 4-wide row fragments. 4x4 register micro-tile per thread.
// gridDim.y = NSPLIT splits over the tw/chunk range for load balance.
// ---------------------------------------------------------------------------
#define LSTR 68

__global__ void __launch_bounds__(256) gemm_argmax_kernel(int n_fb, int n_tw) {
    __shared__ float fbS[64 * LSTR];
    __shared__ float twS[64 * LSTR];
    __shared__ float redV[64 * 16];
    __shared__ int   redI[64 * 16];

    const int tx = threadIdx.x & 15;   // fb micro position (m = tx*4 + i)
    const int ty = threadIdx.x >> 4;   // tw micro position (n = ty*4 + j)
    const int row0 = blockIdx.x * 64;
    const int split = blockIdx.y;

    const int nChunks = (n_tw + 63) >> 6;
    const int per = (nChunks + NSPLIT - 1) / NSPLIT;
    const int c_begin = split * per;
    const int c_end = min(c_begin + per, nChunks);

    // Load fb tile transposed: fbS[k][m] = fbn[row0+m][k]
    for (int idx = threadIdx.x; idx < 64 * 64; idx += 256) {
        int k = idx & 63, m = idx >> 6;
        int gm = row0 + m;
        fbS[k * LSTR + m] = (gm < n_fb) ? g_fbn[(size_t)gm * D + k] : 0.0f;
    }

    float best[4] = {-2.0f, -2.0f, -2.0f, -2.0f};
    int   bidx[4] = {0, 0, 0, 0};

    for (int c = c_begin; c < c_end; c++) {
        __syncthreads();   // prior twS fully consumed (also covers fbS fill on first iter)
        const int col0 = c << 6;
        for (int idx = threadIdx.x; idx < 64 * 64; idx += 256) {
            int k = idx & 63, m = idx >> 6;
            int gn = col0 + m;
            twS[k * LSTR + m] = (gn < n_tw) ? g_twn[(size_t)gn * D + k] : 0.0f;
        }
        __syncthreads();

        float acc[4][4];
        #pragma unroll
        for (int i = 0; i < 4; i++)
            #pragma unroll
            for (int j = 0; j < 4; j++) acc[i][j] = 0.0f;

        #pragma unroll 16
        for (int k = 0; k < 64; k++) {
            float4 a = *reinterpret_cast<const float4*>(&fbS[k * LSTR + tx * 4]);
            float4 b = *reinterpret_cast<const float4*>(&twS[k * LSTR + ty * 4]);
            float av[4] = {a.x, a.y, a.z, a.w};
            float bv[4] = {b.x, b.y, b.z, b.w};
            #pragma unroll
            for (int i = 0; i < 4; i++)
                #pragma unroll
                for (int j = 0; j < 4; j++)
                    acc[i][j] = fmaf(av[i], bv[j], acc[i][j]);
        }

        const int n0 = col0 + ty * 4;
        #pragma unroll
        for (int j = 0; j < 4; j++) {
            int n = n0 + j;
            if (n < n_tw) {
                #pragma unroll
                for (int i = 0; i < 4; i++) {
                    if (acc[i][j] > best[i]) { best[i] = acc[i][j]; bidx[i] = n; }
                }
            }
        }
    }

    __syncthreads();
    #pragma unroll
    for (int i = 0; i < 4; i++) {
        redV[(tx * 4 + i) * 16 + ty] = best[i];
        redI[(tx * 4 + i) * 16 + ty] = bidx[i];
    }
    __syncthreads();

    if (threadIdx.x < 64) {
        int m = threadIdx.x;
        float bv = -3.0f; int bi = 0;
        #pragma unroll
        for (int t = 0; t < 16; t++) {
            float v = redV[m * 16 + t];
            int id = redI[m * 16 + t];
            if (v > bv || (v == bv && id < bi)) { bv = v; bi = id; }
        }
        int gm = row0 + m;
        if (gm < n_fb) {
            g_bestV[split * MAXN + gm] = bv;
            g_bestI[split * MAXN + gm] = bi;
        }
    }
}

// ---------------------------------------------------------------------------
// Phase 3: merge splits + gather tw_sel + attention MLP + softmax +
// weighted sum + output MLP + sigmoid. Warp per fb row, 8 warps/block.
// ---------------------------------------------------------------------------
__global__ void __launch_bounds__(256) head_kernel(
    const float* __restrict__ fb, const float* __restrict__ tw,
    const float* __restrict__ Wa1, const float* __restrict__ ba1,
    const float* __restrict__ Wa2, const float* __restrict__ ba2,
    const float* __restrict__ Wo1, const float* __restrict__ bo1,
    const float* __restrict__ Wo2, const float* __restrict__ bo2,
    float* __restrict__ out, int n_fb) {
    __shared__ float concat[8][128];
    __shared__ float wbuf[8][64];

    int w = threadIdx.x >> 5, lane = threadIdx.x & 31;
    int row = blockIdx.x * 8 + w;
    if (row >= n_fb) return;

    // Merge split-partial argmax results
    float bv = -3.0f; int bi = 0;
    #pragma unroll
    for (int s = 0; s < NSPLIT; s++) {
        float v = g_bestV[s * MAXN + row];
        int id = g_bestI[s * MAXN + row];
        if (v > bv || (v == bv && id < bi)) { bv = v; bi = id; }
    }

    float f0 = fb[(size_t)row * D + lane];
    float f1 = fb[(size_t)row * D + 32 + lane];
    float t0 = tw[(size_t)bi * D + lane];
    float t1 = tw[(size_t)bi * D + 32 + lane];
    concat[w][lane]      = f0;
    concat[w][32 + lane] = f1;
    concat[w][64 + lane] = t0;
    concat[w][96 + lane] = t1;
    __syncwarp();

    // h = relu(concat @ Wa1 + ba1): lane owns units (lane, lane+32)
    float h0 = ba1[lane], h1 = ba1[32 + lane];
    #pragma unroll 8
    for (int k = 0; k < 128; k++) {
        float cv = concat[w][k];
        h0 = fmaf(cv, Wa1[k * 64 + lane], h0);
        h1 = fmaf(cv, Wa1[k * 64 + 32 + lane], h1);
    }
    h0 = fmaxf(h0, 0.0f);
    h1 = fmaxf(h1, 0.0f);

    // logits = h @ Wa2 + ba2 (2-wide), warp reduce
    float p0 = h0 * Wa2[lane * 2 + 0] + h1 * Wa2[(32 + lane) * 2 + 0];
    float p1 = h0 * Wa2[lane * 2 + 1] + h1 * Wa2[(32 + lane) * 2 + 1];
    #pragma unroll
    for (int off = 16; off; off >>= 1) {
        p0 += __shfl_xor_sync(0xffffffffu, p0, off);
        p1 += __shfl_xor_sync(0xffffffffu, p1, off);
    }
    p0 += ba2[0]; p1 += ba2[1];
    float mx = fmaxf(p0, p1);
    float e0 = expf(p0 - mx), e1 = expf(p1 - mx);
    float inv = 1.0f / (e0 + e1);
    float a0 = e0 * inv, a1 = e1 * inv;

    wbuf[w][lane]      = a0 * f0 + a1 * t0;
    wbuf[w][32 + lane] = a0 * f1 + a1 * t1;
    __syncwarp();

    // h2 = relu(weighted @ Wo1 + bo1): lane owns unit `lane` (32 units)
    float g = bo1[lane];
    #pragma unroll 8
    for (int d = 0; d < 64; d++)
        g = fmaf(wbuf[w][d], Wo1[d * 32 + lane], g);
    g = fmaxf(g, 0.0f);

    float o = g * Wo2[lane];
    #pragma unroll
    for (int off = 16; off; off >>= 1) o += __shfl_xor_sync(0xffffffffu, o, off);

    if (lane == 0) out[row] = 1.0f / (1.0f + expf(-(o + bo2[0])));
}

// ---------------------------------------------------------------------------
extern "C" void kernel_launch(void* const* d_in, const int* in_sizes, int n_in,
                              void* d_out, int out_size) {
    const float* fb  = (const float*)d_in[0];
    const float* tw  = (const float*)d_in[1];
    const float* Wa1 = (const float*)d_in[2];
    const float* ba1 = (const float*)d_in[3];
    const float* Wa2 = (const float*)d_in[4];
    const float* ba2 = (const float*)d_in[5];
    const float* Wo1 = (const float*)d_in[6];
    const float* bo1 = (const float*)d_in[7];
    const float* Wo2 = (const float*)d_in[8];
    const float* bo2 = (const float*)d_in[9];
    float* out = (float*)d_out;

    int n_fb = in_sizes[0] / D;
    int n_tw = in_sizes[1] / D;

    float* fbn_ptr; float* twn_ptr;
    cudaGetSymbolAddress((void**)&fbn_ptr, g_fbn);
    cudaGetSymbolAddress((void**)&twn_ptr, g_twn);

    normalize_kernel<<<(n_fb + 7) / 8, 256>>>(fb, fbn_ptr, n_fb);
    normalize_kernel<<<(n_tw + 7) / 8, 256>>>(tw, twn_ptr, n_tw);

    dim3 grid((n_fb + 63) / 64, NSPLIT);
    gemm_argmax_kernel<<<grid, 256>>>(n_fb, n_tw);

    head_kernel<<<(n_fb + 7) / 8, 256>>>(fb, tw, Wa1, ba1, Wa2, ba2,
                                         Wo1, bo1, Wo2, bo2, out, n_fb);
}